// round 3
// baseline (speedup 1.0000x reference)
#include <cuda_runtime.h>

#define BB 512
#define NN 128
#define DD 256
#define TT 512
#define NP (NN + 4)   // padded row stride for N x N smem tiles
#define XP 68         // padded row stride for 64-wide tiles

struct Smem {
    float S[NN][NP];       // assignment matrix S
    float P[NN][NP];       // adj staging, later P = S^T @ adj
    float X[NN][XP];       // streamed 128x64 tile (x or adj columns)
    float w[DD];
    float outv[NN];
    float dis[NN];
    float rfac[NN];        // mask * dis
    float tvec[NN];
    float alpha[NN];
    float colfac[NN];
    unsigned int bits[4];
    float cutv;
    int   kidx;
    int   nuniq;
};

__global__ __launch_bounds__(256, 1)
void graph_coarsen_kernel(const float* __restrict__ x,
                          const float* __restrict__ adj,
                          const int*   __restrict__ head,
                          const float* __restrict__ lw,
                          const float* __restrict__ bias,
                          float* __restrict__ emb,
                          float* __restrict__ nadj)
{
    extern __shared__ char smraw[];
    Smem& sm = *reinterpret_cast<Smem*>(smraw);

    const int b    = blockIdx.x;
    const int tid  = threadIdx.x;
    const int lane = tid & 31;
    const int wid  = tid >> 5;

    const float* adjB = adj + (size_t)b * NN * NN;
    const float* xB   = x   + (size_t)b * NN * DD;

    // ---- stage: weights + adj into smem ----
    sm.w[tid] = lw[tid];  // DD == 256 == blockDim
    {
        const float4* a4 = reinterpret_cast<const float4*>(adjB);
        #pragma unroll
        for (int idx = tid; idx < NN * NN / 4; idx += 256) {
            int k = idx >> 5;
            int c = (idx & 31) << 2;
            *reinterpret_cast<float4*>(&sm.P[k][c]) = a4[idx];
        }
    }
    if (tid < 4) sm.bits[tid] = 0u;
    __syncthreads();

    // ---- out[n] = x[n,:] . w ----
    for (int n = wid; n < NN; n += 8) {
        const float* xr = xB + n * DD;
        float s = 0.f;
        #pragma unroll
        for (int t = 0; t < DD / 32; ++t)
            s = fmaf(xr[lane + 32 * t], sm.w[lane + 32 * t], s);
        #pragma unroll
        for (int o = 16; o > 0; o >>= 1) s += __shfl_down_sync(0xffffffffu, s, o);
        if (lane == 0) sm.outv[n] = s;
    }
    // ---- degree / dis / mask ----
    for (int i = wid; i < NN; i += 8) {
        float s = 0.f;
        #pragma unroll
        for (int t = 0; t < NN / 32; ++t) s += sm.P[i][lane + 32 * t];
        #pragma unroll
        for (int o = 16; o > 0; o >>= 1) s += __shfl_down_sync(0xffffffffu, s, o);
        if (lane == 0) {
            float deg = s + 1.0f;                   // +I on diagonal
            float dv  = rsqrtf(fmaxf(deg, 1.0f));
            sm.dis[i]  = dv;
            sm.rfac[i] = (s > 0.f) ? dv : 0.f;      // row mask * dis
        }
    }
    __syncthreads();

    if (tid < NN) sm.tvec[tid] = sm.dis[tid] * sm.outv[tid];
    {
        int v0 = head[(size_t)b * TT + tid];
        int v1 = head[(size_t)b * TT + 256 + tid];
        atomicOr(&sm.bits[v0 >> 5], 1u << (v0 & 31));
        atomicOr(&sm.bits[v1 >> 5], 1u << (v1 & 31));
    }
    __syncthreads();

    // ---- o2 = norm_adj @ out + bias ; alpha = sigmoid(o2^2) ----
    {
        const float biasv = bias[0];
        for (int i = wid; i < NN; i += 8) {
            float s = 0.f;
            #pragma unroll
            for (int t = 0; t < NN / 32; ++t)
                s = fmaf(sm.P[i][lane + 32 * t], sm.tvec[lane + 32 * t], s);
            #pragma unroll
            for (int o = 16; o > 0; o >>= 1) s += __shfl_down_sync(0xffffffffu, s, o);
            if (lane == 0) {
                float o2 = fmaf(sm.rfac[i], s + sm.tvec[i], biasv);
                float q  = o2 * o2;
                sm.alpha[i] = 1.0f / (1.0f + expf(-q));
            }
        }
    }
    if (tid == 0) {
        int nu = __popc(sm.bits[0]) + __popc(sm.bits[1]) +
                 __popc(sm.bits[2]) + __popc(sm.bits[3]);
        sm.nuniq = nu;
        int k   = (int)ceilf((float)nu * 0.1f) + 1;
        int idx = k - 1;
        if (idx < 0) idx = 0;
        if (idx > NN - 1) idx = NN - 1;
        sm.kidx = idx;
    }
    __syncthreads();

    // ---- cut = k-th largest alpha (rank with stable tie-break) ----
    if (tid < NN) {
        float ai = sm.alpha[tid];
        int cnt = 0;
        #pragma unroll 8
        for (int j = 0; j < NN; ++j) {
            float aj = sm.alpha[j];
            cnt += (aj > ai) || (aj == ai && j < tid);
        }
        if (cnt == sm.kidx) sm.cutv = (sm.nuniq > 1) ? ai : 0.f;
    }
    __syncthreads();
    if (tid < NN) {
        float ca = fmaxf(sm.alpha[tid] + 1e-7f - sm.cutv, 0.f);
        sm.colfac[tid] = sm.dis[tid] * ca;
    }
    __syncthreads();

    // ---- build S in smem: S[i,j] = r2[i] * (adj[i,j] + d_ij) * colfac[j] ----
    for (int i = wid; i < NN; i += 8) {
        float s = 0.f;
        #pragma unroll
        for (int t = 0; t < NN / 32; ++t)
            s = fmaf(sm.P[i][lane + 32 * t], sm.colfac[lane + 32 * t], s);
        #pragma unroll
        for (int o = 16; o > 0; o >>= 1) s += __shfl_down_sync(0xffffffffu, s, o);
        s = __shfl_sync(0xffffffffu, s, 0);
        float rf  = sm.rfac[i];
        float tot = rf * (s + sm.colfac[i]);       // L1 row sum (all nonneg)
        float r2  = rf / fmaxf(tot, 1e-12f);
        #pragma unroll
        for (int t = 0; t < NN / 32; ++t) {
            int j = lane + 32 * t;
            float a = sm.P[i][j] + ((j == i) ? 1.f : 0.f);
            sm.S[i][j] = r2 * a * sm.colfac[j];
        }
    }
    __syncthreads();

    const int ty = tid >> 4, tx = tid & 15;
    const int i0 = ty * 8;

    // ---- GEMM1: emb = S^T @ x  (4 chunks of 64 d-cols) ----
    {
        float* embB = emb + (size_t)b * NN * DD;
        const int dd = tx * 4;
        for (int dc = 0; dc < 4; ++dc) {
            const int d0 = dc * 64;
            for (int idx = tid; idx < NN * 16; idx += 256) {
                int k = idx >> 4, c = (idx & 15) << 2;
                *reinterpret_cast<float4*>(&sm.X[k][c]) =
                    *reinterpret_cast<const float4*>(&xB[k * DD + d0 + c]);
            }
            __syncthreads();
            float acc[8][4];
            #pragma unroll
            for (int r = 0; r < 8; ++r)
                #pragma unroll
                for (int c = 0; c < 4; ++c) acc[r][c] = 0.f;
            for (int k = 0; k < NN; ++k) {
                float4 a0 = *reinterpret_cast<float4*>(&sm.S[k][i0]);
                float4 a1 = *reinterpret_cast<float4*>(&sm.S[k][i0 + 4]);
                float4 bv = *reinterpret_cast<float4*>(&sm.X[k][dd]);
                float a_[8] = {a0.x, a0.y, a0.z, a0.w, a1.x, a1.y, a1.z, a1.w};
                float b_[4] = {bv.x, bv.y, bv.z, bv.w};
                #pragma unroll
                for (int r = 0; r < 8; ++r)
                    #pragma unroll
                    for (int c = 0; c < 4; ++c)
                        acc[r][c] = fmaf(a_[r], b_[c], acc[r][c]);
            }
            #pragma unroll
            for (int r = 0; r < 8; ++r) {
                float4 v = {acc[r][0], acc[r][1], acc[r][2], acc[r][3]};
                *reinterpret_cast<float4*>(&embB[(i0 + r) * DD + d0 + dd]) = v;
            }
            __syncthreads();
        }
    }

    // ---- GEMM2: P = S^T @ adj  (adj streamed from global, overwrites staging) ----
    {
        const int jj = tx * 4;
        for (int jc = 0; jc < 2; ++jc) {
            const int j0 = jc * 64;
            for (int idx = tid; idx < NN * 16; idx += 256) {
                int k = idx >> 4, c = (idx & 15) << 2;
                *reinterpret_cast<float4*>(&sm.X[k][c]) =
                    *reinterpret_cast<const float4*>(&adjB[k * NN + j0 + c]);
            }
            __syncthreads();
            float acc[8][4];
            #pragma unroll
            for (int r = 0; r < 8; ++r)
                #pragma unroll
                for (int c = 0; c < 4; ++c) acc[r][c] = 0.f;
            for (int k = 0; k < NN; ++k) {
                float4 a0 = *reinterpret_cast<float4*>(&sm.S[k][i0]);
                float4 a1 = *reinterpret_cast<float4*>(&sm.S[k][i0 + 4]);
                float4 bv = *reinterpret_cast<float4*>(&sm.X[k][jj]);
                float a_[8] = {a0.x, a0.y, a0.z, a0.w, a1.x, a1.y, a1.z, a1.w};
                float b_[4] = {bv.x, bv.y, bv.z, bv.w};
                #pragma unroll
                for (int r = 0; r < 8; ++r)
                    #pragma unroll
                    for (int c = 0; c < 4; ++c)
                        acc[r][c] = fmaf(a_[r], b_[c], acc[r][c]);
            }
            __syncthreads();   // make sure all reads of X done before overwrite next iter; P writes below are disjoint
            #pragma unroll
            for (int r = 0; r < 8; ++r) {
                float4 v = {acc[r][0], acc[r][1], acc[r][2], acc[r][3]};
                *reinterpret_cast<float4*>(&sm.P[i0 + r][j0 + jj]) = v;
            }
        }
        __syncthreads();
    }

    // ---- GEMM3: new_adj = P @ S ----
    {
        const int j0 = tx * 8;
        float acc[8][8];
        #pragma unroll
        for (int r = 0; r < 8; ++r)
            #pragma unroll
            for (int c = 0; c < 8; ++c) acc[r][c] = 0.f;
        for (int k = 0; k < NN; ++k) {
            float4 b0 = *reinterpret_cast<float4*>(&sm.S[k][j0]);
            float4 b1 = *reinterpret_cast<float4*>(&sm.S[k][j0 + 4]);
            float b_[8] = {b0.x, b0.y, b0.z, b0.w, b1.x, b1.y, b1.z, b1.w};
            float a_[8];
            #pragma unroll
            for (int r = 0; r < 8; ++r) a_[r] = sm.P[i0 + r][k];
            #pragma unroll
            for (int r = 0; r < 8; ++r)
                #pragma unroll
                for (int c = 0; c < 8; ++c)
                    acc[r][c] = fmaf(a_[r], b_[c], acc[r][c]);
        }
        float* nadjB = nadj + (size_t)b * NN * NN;
        #pragma unroll
        for (int r = 0; r < 8; ++r) {
            float4 v0 = {acc[r][0], acc[r][1], acc[r][2], acc[r][3]};
            float4 v1 = {acc[r][4], acc[r][5], acc[r][6], acc[r][7]};
            *reinterpret_cast<float4*>(&nadjB[(i0 + r) * NN + j0])     = v0;
            *reinterpret_cast<float4*>(&nadjB[(i0 + r) * NN + j0 + 4]) = v1;
        }
    }
}

extern "C" void kernel_launch(void* const* d_in, const int* in_sizes, int n_in,
                              void* d_out, int out_size) {
    const float* x    = (const float*)d_in[0];   // concept_hidden [B,N,D]
    const float* adj  = (const float*)d_in[1];   // adj [B,N,N]
    const int*   head = (const int*)d_in[2];     // head [B,T]
    const float* lw   = (const float*)d_in[3];   // lin_w [1,D]
    const float* bias = (const float*)d_in[4];   // bias [1]

    float* out  = (float*)d_out;
    float* emb  = out;                                  // [B,N,D]
    float* nadj = out + (size_t)BB * NN * DD;           // [B,N,N]

    const int smemBytes = (int)sizeof(Smem);
    cudaFuncSetAttribute(graph_coarsen_kernel,
                         cudaFuncAttributeMaxDynamicSharedMemorySize, smemBytes);
    graph_coarsen_kernel<<<BB, 256, smemBytes>>>(x, adj, head, lw, bias, emb, nadj);
}

// round 4
// speedup vs baseline: 1.0781x; 1.0781x over previous
#include <cuda_runtime.h>

#define BB 512
#define NN 128
#define DD 256
#define TT 512
#define NP (NN + 4)   // padded row stride for S
#define XP 68         // padded row stride for 64-wide tiles

struct Smem {
    float S[NN][NP];       // assignment matrix S           (67.6 KB)
    float X[NN][XP];       // streamed 128x64 tile / Y      (34.8 KB)
    float w[DD];
    float outv[NN];
    float dis[NN];
    float rfac[NN];        // mask * dis
    float tvec[NN];
    float alpha[NN];
    float colfac[NN];
    unsigned int bits[4];
    float cutv;
    int   kidx;
    int   nuniq;
};

__global__ __launch_bounds__(256, 2)
void graph_coarsen_kernel(const float* __restrict__ x,
                          const float* __restrict__ adj,
                          const int*   __restrict__ head,
                          const float* __restrict__ lw,
                          const float* __restrict__ bias,
                          float* __restrict__ emb,
                          float* __restrict__ nadj)
{
    extern __shared__ char smraw[];
    Smem& sm = *reinterpret_cast<Smem*>(smraw);

    const int b    = blockIdx.x;
    const int tid  = threadIdx.x;
    const int lane = tid & 31;
    const int wid  = tid >> 5;

    const float* adjB = adj + (size_t)b * NN * NN;
    const float* xB   = x   + (size_t)b * NN * DD;

    sm.w[tid] = lw[tid];  // DD == 256 == blockDim
    if (tid < 4) sm.bits[tid] = 0u;
    __syncthreads();

    // ---- out[n] = x[n,:] . w ----
    for (int n = wid; n < NN; n += 8) {
        const float* xr = xB + n * DD;
        float s = 0.f;
        #pragma unroll
        for (int t = 0; t < DD / 32; ++t)
            s = fmaf(xr[lane + 32 * t], sm.w[lane + 32 * t], s);
        #pragma unroll
        for (int o = 16; o > 0; o >>= 1) s += __shfl_down_sync(0xffffffffu, s, o);
        if (lane == 0) sm.outv[n] = s;
    }
    // ---- degree / dis / mask (adj from global, coalesced) ----
    for (int i = wid; i < NN; i += 8) {
        const float* ar = adjB + i * NN;
        float s = 0.f;
        #pragma unroll
        for (int t = 0; t < NN / 32; ++t) s += ar[lane + 32 * t];
        #pragma unroll
        for (int o = 16; o > 0; o >>= 1) s += __shfl_down_sync(0xffffffffu, s, o);
        if (lane == 0) {
            float deg = s + 1.0f;
            float dv  = rsqrtf(fmaxf(deg, 1.0f));
            sm.dis[i]  = dv;
            sm.rfac[i] = (s > 0.f) ? dv : 0.f;
        }
    }
    __syncthreads();

    if (tid < NN) sm.tvec[tid] = sm.dis[tid] * sm.outv[tid];
    {
        int v0 = head[(size_t)b * TT + tid];
        int v1 = head[(size_t)b * TT + 256 + tid];
        atomicOr(&sm.bits[v0 >> 5], 1u << (v0 & 31));
        atomicOr(&sm.bits[v1 >> 5], 1u << (v1 & 31));
    }
    __syncthreads();

    // ---- o2 = norm_adj @ out + bias ; alpha = sigmoid(o2^2) ----
    {
        const float biasv = bias[0];
        for (int i = wid; i < NN; i += 8) {
            const float* ar = adjB + i * NN;
            float s = 0.f;
            #pragma unroll
            for (int t = 0; t < NN / 32; ++t)
                s = fmaf(ar[lane + 32 * t], sm.tvec[lane + 32 * t], s);
            #pragma unroll
            for (int o = 16; o > 0; o >>= 1) s += __shfl_down_sync(0xffffffffu, s, o);
            if (lane == 0) {
                float o2 = fmaf(sm.rfac[i], s + sm.tvec[i], biasv);
                float q  = o2 * o2;
                sm.alpha[i] = 1.0f / (1.0f + expf(-q));
            }
        }
    }
    if (tid == 0) {
        int nu = __popc(sm.bits[0]) + __popc(sm.bits[1]) +
                 __popc(sm.bits[2]) + __popc(sm.bits[3]);
        sm.nuniq = nu;
        int k   = (int)ceilf((float)nu * 0.1f) + 1;
        int idx = k - 1;
        if (idx < 0) idx = 0;
        if (idx > NN - 1) idx = NN - 1;
        sm.kidx = idx;
    }
    __syncthreads();

    // ---- cut = k-th largest alpha (rank with stable tie-break) ----
    if (tid < NN) {
        float ai = sm.alpha[tid];
        int cnt = 0;
        #pragma unroll 8
        for (int j = 0; j < NN; ++j) {
            float aj = sm.alpha[j];
            cnt += (aj > ai) || (aj == ai && j < tid);
        }
        if (cnt == sm.kidx) sm.cutv = (sm.nuniq > 1) ? ai : 0.f;
    }
    __syncthreads();
    if (tid < NN) {
        float ca = fmaxf(sm.alpha[tid] + 1e-7f - sm.cutv, 0.f);
        sm.colfac[tid] = sm.dis[tid] * ca;
    }
    __syncthreads();

    // ---- build S: S[i,j] = rfac[i]*(adj+I)_ij*colfac[j], row-L1-normalized ----
    for (int i = wid; i < NN; i += 8) {
        const float* ar = adjB + i * NN;
        float v[NN / 32];
        float s = 0.f;
        #pragma unroll
        for (int t = 0; t < NN / 32; ++t) {
            int j = lane + 32 * t;
            float a = ar[j] + ((j == i) ? 1.f : 0.f);
            v[t] = a * sm.colfac[j];
            s += v[t];
        }
        #pragma unroll
        for (int o = 16; o > 0; o >>= 1) s += __shfl_down_sync(0xffffffffu, s, o);
        s = __shfl_sync(0xffffffffu, s, 0);
        float rf  = sm.rfac[i];
        float tot = rf * s;                       // L1 row sum (all nonneg)
        float r2  = rf / fmaxf(tot, 1e-12f);
        #pragma unroll
        for (int t = 0; t < NN / 32; ++t)
            sm.S[i][lane + 32 * t] = r2 * v[t];
    }
    __syncthreads();

    const int ty = tid >> 4, tx = tid & 15;
    const int i0 = ty * 8;

    // ---- GEMM1: emb = S^T @ x  (4 chunks of 64 d-cols through X) ----
    {
        float* embB = emb + (size_t)b * NN * DD;
        const int dd = tx * 4;
        for (int dc = 0; dc < 4; ++dc) {
            const int d0 = dc * 64;
            for (int idx = tid; idx < NN * 16; idx += 256) {
                int k = idx >> 4, c = (idx & 15) << 2;
                *reinterpret_cast<float4*>(&sm.X[k][c]) =
                    *reinterpret_cast<const float4*>(&xB[k * DD + d0 + c]);
            }
            __syncthreads();
            float acc[8][4];
            #pragma unroll
            for (int r = 0; r < 8; ++r)
                #pragma unroll
                for (int c = 0; c < 4; ++c) acc[r][c] = 0.f;
            for (int k = 0; k < NN; ++k) {
                float4 a0 = *reinterpret_cast<float4*>(&sm.S[k][i0]);
                float4 a1 = *reinterpret_cast<float4*>(&sm.S[k][i0 + 4]);
                float4 bv = *reinterpret_cast<float4*>(&sm.X[k][dd]);
                float a_[8] = {a0.x, a0.y, a0.z, a0.w, a1.x, a1.y, a1.z, a1.w};
                float b_[4] = {bv.x, bv.y, bv.z, bv.w};
                #pragma unroll
                for (int r = 0; r < 8; ++r)
                    #pragma unroll
                    for (int c = 0; c < 4; ++c)
                        acc[r][c] = fmaf(a_[r], b_[c], acc[r][c]);
            }
            #pragma unroll
            for (int r = 0; r < 8; ++r) {
                float4 v = {acc[r][0], acc[r][1], acc[r][2], acc[r][3]};
                *reinterpret_cast<float4*>(&embB[(i0 + r) * DD + d0 + dd]) = v;
            }
            __syncthreads();
        }
    }

    // ---- new_adj = S^T (adj S): per 64-col chunk, Y = adj@S_chunk into X,
    //      then nadj_chunk = S^T @ Y ----
    {
        float* nadjB = nadj + (size_t)b * NN * NN;
        const int jj = tx * 4;
        for (int jc = 0; jc < 2; ++jc) {
            const int j0 = jc * 64;

            // Y[i, jj..jj+3] for i = i0..i0+7:  Y = adj @ S[:, j0:j0+64]
            float acc[8][4];
            #pragma unroll
            for (int r = 0; r < 8; ++r)
                #pragma unroll
                for (int c = 0; c < 4; ++c) acc[r][c] = 0.f;
            for (int k4 = 0; k4 < NN; k4 += 4) {
                float4 bv[4];
                #pragma unroll
                for (int kk = 0; kk < 4; ++kk)
                    bv[kk] = *reinterpret_cast<float4*>(&sm.S[k4 + kk][j0 + jj]);
                float4 av[8];
                #pragma unroll
                for (int r = 0; r < 8; ++r)
                    av[r] = *reinterpret_cast<const float4*>(&adjB[(i0 + r) * NN + k4]);
                #pragma unroll
                for (int r = 0; r < 8; ++r) {
                    float ar_[4] = {av[r].x, av[r].y, av[r].z, av[r].w};
                    #pragma unroll
                    for (int kk = 0; kk < 4; ++kk) {
                        acc[r][0] = fmaf(ar_[kk], bv[kk].x, acc[r][0]);
                        acc[r][1] = fmaf(ar_[kk], bv[kk].y, acc[r][1]);
                        acc[r][2] = fmaf(ar_[kk], bv[kk].z, acc[r][2]);
                        acc[r][3] = fmaf(ar_[kk], bv[kk].w, acc[r][3]);
                    }
                }
            }
            __syncthreads();   // GEMM1 / previous chunk readers of X are done
            #pragma unroll
            for (int r = 0; r < 8; ++r) {
                float4 v = {acc[r][0], acc[r][1], acc[r][2], acc[r][3]};
                *reinterpret_cast<float4*>(&sm.X[i0 + r][jj]) = v;
            }
            __syncthreads();

            // nadj[:, j0:j0+64] = S^T @ Y
            float acc2[8][4];
            #pragma unroll
            for (int r = 0; r < 8; ++r)
                #pragma unroll
                for (int c = 0; c < 4; ++c) acc2[r][c] = 0.f;
            for (int k = 0; k < NN; ++k) {
                float4 a0 = *reinterpret_cast<float4*>(&sm.S[k][i0]);
                float4 a1 = *reinterpret_cast<float4*>(&sm.S[k][i0 + 4]);
                float4 bv = *reinterpret_cast<float4*>(&sm.X[k][jj]);
                float a_[8] = {a0.x, a0.y, a0.z, a0.w, a1.x, a1.y, a1.z, a1.w};
                float b_[4] = {bv.x, bv.y, bv.z, bv.w};
                #pragma unroll
                for (int r = 0; r < 8; ++r)
                    #pragma unroll
                    for (int c = 0; c < 4; ++c)
                        acc2[r][c] = fmaf(a_[r], b_[c], acc2[r][c]);
            }
            #pragma unroll
            for (int r = 0; r < 8; ++r) {
                float4 v = {acc2[r][0], acc2[r][1], acc2[r][2], acc2[r][3]};
                *reinterpret_cast<float4*>(&nadjB[(i0 + r) * NN + j0 + jj]) = v;
            }
            __syncthreads();
        }
    }
}

extern "C" void kernel_launch(void* const* d_in, const int* in_sizes, int n_in,
                              void* d_out, int out_size) {
    const float* x    = (const float*)d_in[0];   // concept_hidden [B,N,D]
    const float* adj  = (const float*)d_in[1];   // adj [B,N,N]
    const int*   head = (const int*)d_in[2];     // head [B,T]
    const float* lw   = (const float*)d_in[3];   // lin_w [1,D]
    const float* bias = (const float*)d_in[4];   // bias [1]

    float* out  = (float*)d_out;
    float* emb  = out;                                  // [B,N,D]
    float* nadj = out + (size_t)BB * NN * DD;           // [B,N,N]

    const int smemBytes = (int)sizeof(Smem);
    cudaFuncSetAttribute(graph_coarsen_kernel,
                         cudaFuncAttributeMaxDynamicSharedMemorySize, smemBytes);
    graph_coarsen_kernel<<<BB, 256, smemBytes>>>(x, adj, head, lw, bias, emb, nadj);
}

// round 6
// speedup vs baseline: 1.3181x; 1.2225x over previous
#include <cuda_runtime.h>

#define BB 512
#define NN 128
#define DD 256
#define TT 512
#define NP (NN + 4)   // padded row stride for S (rows stay 16B aligned: 132*4=528=33*16)
#define XP 68         // padded row stride for 64-wide tiles

typedef unsigned long long u64t;

#define FMA2(acc, a, b) \
    asm("fma.rn.f32x2 %0, %1, %2, %0;" : "+l"(acc) : "l"(a), "l"(b))
#define PACK2(out, v) \
    asm("mov.b64 %0, {%1, %1};" : "=l"(out) : "r"(__float_as_uint(v)))

__device__ __forceinline__ float lo32(u64t v) { return __uint_as_float((unsigned)v); }
__device__ __forceinline__ float hi32(u64t v) { return __uint_as_float((unsigned)(v >> 32)); }

struct Smem {
    float S[NN][NP];       // assignment matrix S           (67.6 KB)
    float X[NN][XP];       // streamed 128x64 tile / Y      (34.8 KB)
    float w[DD];
    float outv[NN];
    float dis[NN];
    float rfac[NN];        // mask * dis
    float tvec[NN];
    float alpha[NN];
    float colfac[NN];
    unsigned int bits[4];
    float cutv;
    int   kidx;
    int   nuniq;
};

__global__ __launch_bounds__(256, 2)
void graph_coarsen_kernel(const float* __restrict__ x,
                          const float* __restrict__ adj,
                          const int*   __restrict__ head,
                          const float* __restrict__ lw,
                          const float* __restrict__ bias,
                          float* __restrict__ emb,
                          float* __restrict__ nadj)
{
    extern __shared__ char smraw[];
    Smem& sm = *reinterpret_cast<Smem*>(smraw);

    const int b    = blockIdx.x;
    const int tid  = threadIdx.x;
    const int lane = tid & 31;
    const int wid  = tid >> 5;

    const float* adjB = adj + (size_t)b * NN * NN;
    const float* xB   = x   + (size_t)b * NN * DD;

    sm.w[tid] = lw[tid];  // DD == 256 == blockDim
    if (tid < 4) sm.bits[tid] = 0u;
    __syncthreads();

    // ---- out[n] = x[n,:] . w ----
    for (int n = wid; n < NN; n += 8) {
        const float* xr = xB + n * DD;
        float s = 0.f;
        #pragma unroll
        for (int t = 0; t < DD / 32; ++t)
            s = fmaf(xr[lane + 32 * t], sm.w[lane + 32 * t], s);
        #pragma unroll
        for (int o = 16; o > 0; o >>= 1) s += __shfl_down_sync(0xffffffffu, s, o);
        if (lane == 0) sm.outv[n] = s;
    }
    // ---- degree / dis / mask (adj from global, coalesced) ----
    for (int i = wid; i < NN; i += 8) {
        const float* ar = adjB + i * NN;
        float s = 0.f;
        #pragma unroll
        for (int t = 0; t < NN / 32; ++t) s += ar[lane + 32 * t];
        #pragma unroll
        for (int o = 16; o > 0; o >>= 1) s += __shfl_down_sync(0xffffffffu, s, o);
        if (lane == 0) {
            float deg = s + 1.0f;
            float dv  = rsqrtf(fmaxf(deg, 1.0f));
            sm.dis[i]  = dv;
            sm.rfac[i] = (s > 0.f) ? dv : 0.f;
        }
    }
    __syncthreads();

    if (tid < NN) sm.tvec[tid] = sm.dis[tid] * sm.outv[tid];
    {
        int v0 = head[(size_t)b * TT + tid];
        int v1 = head[(size_t)b * TT + 256 + tid];
        atomicOr(&sm.bits[v0 >> 5], 1u << (v0 & 31));
        atomicOr(&sm.bits[v1 >> 5], 1u << (v1 & 31));
    }
    __syncthreads();

    // ---- o2 = norm_adj @ out + bias ; alpha = sigmoid(o2^2) ----
    {
        const float biasv = bias[0];
        for (int i = wid; i < NN; i += 8) {
            const float* ar = adjB + i * NN;
            float s = 0.f;
            #pragma unroll
            for (int t = 0; t < NN / 32; ++t)
                s = fmaf(ar[lane + 32 * t], sm.tvec[lane + 32 * t], s);
            #pragma unroll
            for (int o = 16; o > 0; o >>= 1) s += __shfl_down_sync(0xffffffffu, s, o);
            if (lane == 0) {
                float o2 = fmaf(sm.rfac[i], s + sm.tvec[i], biasv);
                float q  = o2 * o2;
                sm.alpha[i] = 1.0f / (1.0f + expf(-q));
            }
        }
    }
    if (tid == 0) {
        int nu = __popc(sm.bits[0]) + __popc(sm.bits[1]) +
                 __popc(sm.bits[2]) + __popc(sm.bits[3]);
        sm.nuniq = nu;
        int k   = (int)ceilf((float)nu * 0.1f) + 1;
        int idx = k - 1;
        if (idx < 0) idx = 0;
        if (idx > NN - 1) idx = NN - 1;
        sm.kidx = idx;
    }
    __syncthreads();

    // ---- cut = k-th largest alpha (rank with stable tie-break) ----
    if (tid < NN) {
        float ai = sm.alpha[tid];
        int cnt = 0;
        #pragma unroll 8
        for (int j = 0; j < NN; ++j) {
            float aj = sm.alpha[j];
            cnt += (aj > ai) || (aj == ai && j < tid);
        }
        if (cnt == sm.kidx) sm.cutv = (sm.nuniq > 1) ? ai : 0.f;
    }
    __syncthreads();
    if (tid < NN) {
        float ca = fmaxf(sm.alpha[tid] + 1e-7f - sm.cutv, 0.f);
        sm.colfac[tid] = sm.dis[tid] * ca;
    }
    __syncthreads();

    // ---- build S: S[i,j] = rfac[i]*(adj+I)_ij*colfac[j], row-L1-normalized ----
    for (int i = wid; i < NN; i += 8) {
        const float* ar = adjB + i * NN;
        float v[NN / 32];
        float s = 0.f;
        #pragma unroll
        for (int t = 0; t < NN / 32; ++t) {
            int j = lane + 32 * t;
            float a = ar[j] + ((j == i) ? 1.f : 0.f);
            v[t] = a * sm.colfac[j];
            s += v[t];
        }
        #pragma unroll
        for (int o = 16; o > 0; o >>= 1) s += __shfl_down_sync(0xffffffffu, s, o);
        s = __shfl_sync(0xffffffffu, s, 0);
        float rf  = sm.rfac[i];
        float tot = rf * s;                       // L1 row sum (all nonneg)
        float r2  = rf / fmaxf(tot, 1e-12f);
        #pragma unroll
        for (int t = 0; t < NN / 32; ++t)
            sm.S[i][lane + 32 * t] = r2 * v[t];
    }
    __syncthreads();

    const int ty = tid >> 4, tx = tid & 15;
    const int i0 = ty * 8;

    // ---- GEMM1: emb = S^T @ x  (4 chunks of 64 d-cols through X) ----
    // packed over row-pairs: A pairs free from LDS.128 of S rows.
    {
        float* embB = emb + (size_t)b * NN * DD;
        const int dd = tx * 4;
        for (int dc = 0; dc < 4; ++dc) {
            const int d0 = dc * 64;
            for (int idx = tid; idx < NN * 16; idx += 256) {
                int k = idx >> 4, c = (idx & 15) << 2;
                *reinterpret_cast<float4*>(&sm.X[k][c]) =
                    *reinterpret_cast<const float4*>(&xB[k * DD + d0 + c]);
            }
            __syncthreads();
            u64t acc[4][4];
            #pragma unroll
            for (int p = 0; p < 4; ++p)
                #pragma unroll
                for (int c = 0; c < 4; ++c) acc[p][c] = 0ull;
            #pragma unroll 2
            for (int k = 0; k < NN; ++k) {
                ulonglong2 A0 = *reinterpret_cast<ulonglong2*>(&sm.S[k][i0]);
                ulonglong2 A1 = *reinterpret_cast<ulonglong2*>(&sm.S[k][i0 + 4]);
                float4 bv = *reinterpret_cast<float4*>(&sm.X[k][dd]);
                u64t Bp[4];
                PACK2(Bp[0], bv.x); PACK2(Bp[1], bv.y);
                PACK2(Bp[2], bv.z); PACK2(Bp[3], bv.w);
                u64t Ap[4] = {A0.x, A0.y, A1.x, A1.y};
                #pragma unroll
                for (int p = 0; p < 4; ++p)
                    #pragma unroll
                    for (int c = 0; c < 4; ++c)
                        FMA2(acc[p][c], Ap[p], Bp[c]);
            }
            #pragma unroll
            for (int p = 0; p < 4; ++p) {
                float4 v0 = {lo32(acc[p][0]), lo32(acc[p][1]), lo32(acc[p][2]), lo32(acc[p][3])};
                float4 v1 = {hi32(acc[p][0]), hi32(acc[p][1]), hi32(acc[p][2]), hi32(acc[p][3])};
                *reinterpret_cast<float4*>(&embB[(i0 + 2 * p)     * DD + d0 + dd]) = v0;
                *reinterpret_cast<float4*>(&embB[(i0 + 2 * p + 1) * DD + d0 + dd]) = v1;
            }
            __syncthreads();
        }
    }

    // ---- new_adj = S^T (adj S): per 64-col chunk, Y = adj@S_chunk into X,
    //      then nadj_chunk = S^T @ Y ----
    {
        float* nadjB = nadj + (size_t)b * NN * NN;
        const int jj = tx * 4;
        for (int jc = 0; jc < 2; ++jc) {
            const int j0 = jc * 64;

            // Y[i0..i0+7, jj..jj+3] = adj @ S[:, j0:j0+64]
            // packed over col-pairs: B pairs free from LDS.128 of S rows.
            u64t accY[8][2];
            #pragma unroll
            for (int r = 0; r < 8; ++r) { accY[r][0] = 0ull; accY[r][1] = 0ull; }
            for (int k4 = 0; k4 < NN; k4 += 4) {
                ulonglong2 Bk[4];
                #pragma unroll
                for (int kk = 0; kk < 4; ++kk)
                    Bk[kk] = *reinterpret_cast<ulonglong2*>(&sm.S[k4 + kk][j0 + jj]);
                float4 av[8];
                #pragma unroll
                for (int r = 0; r < 8; ++r)
                    av[r] = *reinterpret_cast<const float4*>(&adjB[(i0 + r) * NN + k4]);
                #pragma unroll
                for (int kk = 0; kk < 4; ++kk) {
                    #pragma unroll
                    for (int r = 0; r < 8; ++r) {
                        float as = (kk == 0) ? av[r].x : (kk == 1) ? av[r].y
                                 : (kk == 2) ? av[r].z : av[r].w;
                        u64t pa;
                        PACK2(pa, as);
                        FMA2(accY[r][0], pa, Bk[kk].x);
                        FMA2(accY[r][1], pa, Bk[kk].y);
                    }
                }
            }
            __syncthreads();   // previous readers of X are done
            #pragma unroll
            for (int r = 0; r < 8; ++r) {
                float4 v = {lo32(accY[r][0]), hi32(accY[r][0]),
                            lo32(accY[r][1]), hi32(accY[r][1])};
                *reinterpret_cast<float4*>(&sm.X[i0 + r][jj]) = v;
            }
            __syncthreads();

            // nadj[:, j0:j0+64] = S^T @ Y   (row-pair packed like GEMM1)
            u64t acc[4][4];
            #pragma unroll
            for (int p = 0; p < 4; ++p)
                #pragma unroll
                for (int c = 0; c < 4; ++c) acc[p][c] = 0ull;
            #pragma unroll 2
            for (int k = 0; k < NN; ++k) {
                ulonglong2 A0 = *reinterpret_cast<ulonglong2*>(&sm.S[k][i0]);
                ulonglong2 A1 = *reinterpret_cast<ulonglong2*>(&sm.S[k][i0 + 4]);
                float4 bv = *reinterpret_cast<float4*>(&sm.X[k][jj]);
                u64t Bp[4];
                PACK2(Bp[0], bv.x); PACK2(Bp[1], bv.y);
                PACK2(Bp[2], bv.z); PACK2(Bp[3], bv.w);
                u64t Ap[4] = {A0.x, A0.y, A1.x, A1.y};
                #pragma unroll
                for (int p = 0; p < 4; ++p)
                    #pragma unroll
                    for (int c = 0; c < 4; ++c)
                        FMA2(acc[p][c], Ap[p], Bp[c]);
            }
            #pragma unroll
            for (int p = 0; p < 4; ++p) {
                float4 v0 = {lo32(acc[p][0]), lo32(acc[p][1]), lo32(acc[p][2]), lo32(acc[p][3])};
                float4 v1 = {hi32(acc[p][0]), hi32(acc[p][1]), hi32(acc[p][2]), hi32(acc[p][3])};
                *reinterpret_cast<float4*>(&nadjB[(i0 + 2 * p)     * NN + j0 + jj]) = v0;
                *reinterpret_cast<float4*>(&nadjB[(i0 + 2 * p + 1) * NN + j0 + jj]) = v1;
            }
            __syncthreads();
        }
    }
}

extern "C" void kernel_launch(void* const* d_in, const int* in_sizes, int n_in,
                              void* d_out, int out_size) {
    const float* x    = (const float*)d_in[0];   // concept_hidden [B,N,D]
    const float* adj  = (const float*)d_in[1];   // adj [B,N,N]
    const int*   head = (const int*)d_in[2];     // head [B,T]
    const float* lw   = (const float*)d_in[3];   // lin_w [1,D]
    const float* bias = (const float*)d_in[4];   // bias [1]

    float* out  = (float*)d_out;
    float* emb  = out;                                  // [B,N,D]
    float* nadj = out + (size_t)BB * NN * DD;           // [B,N,N]

    const int smemBytes = (int)sizeof(Smem);
    cudaFuncSetAttribute(graph_coarsen_kernel,
                         cudaFuncAttributeMaxDynamicSharedMemorySize, smemBytes);
    graph_coarsen_kernel<<<BB, 256, smemBytes>>>(x, adj, head, lw, bias, emb, nadj);
}

// round 7
// speedup vs baseline: 1.9489x; 1.4786x over previous
#include <cuda_runtime.h>

#define BB 512
#define NN 128
#define DD 256
#define TT 512
#define NP (NN + 4)   // padded row stride for S (rows stay 16B aligned)
#define XP 68         // padded row stride for 64-wide tiles

typedef unsigned long long u64t;

#define FMA2(acc, a, b) \
    asm("fma.rn.f32x2 %0, %1, %2, %0;" : "+l"(acc) : "l"(a), "l"(b))
#define PACK2(out, v) \
    asm("mov.b64 %0, {%1, %1};" : "=l"(out) : "r"(__float_as_uint(v)))

__device__ __forceinline__ float lo32(u64t v) { return __uint_as_float((unsigned)v); }
__device__ __forceinline__ float hi32(u64t v) { return __uint_as_float((unsigned)(v >> 32)); }

struct Smem {
    float S[NN][NP];       // assignment matrix S           (67.6 KB)
    float X[NN][XP];       // streamed 128x64 tile / Y      (34.8 KB)
    float w[DD];
    float outv[NN];
    float dis[NN];
    float rfac[NN];        // mask * dis
    float tvec[NN];
    float alpha[NN];
    float colfac[NN];
    unsigned int bits[4];
    float cutv;
    int   kidx;
    int   nuniq;
};

__global__ __launch_bounds__(256, 2)
void graph_coarsen_kernel(const float* __restrict__ x,
                          const float* __restrict__ adj,
                          const int*   __restrict__ head,
                          const float* __restrict__ lw,
                          const float* __restrict__ bias,
                          float* __restrict__ emb,
                          float* __restrict__ nadj)
{
    extern __shared__ char smraw[];
    Smem& sm = *reinterpret_cast<Smem*>(smraw);

    const int b    = blockIdx.x;
    const int tid  = threadIdx.x;
    const int lane = tid & 31;
    const int wid  = tid >> 5;

    const float* adjB = adj + (size_t)b * NN * NN;
    const float* xB   = x   + (size_t)b * NN * DD;

    sm.w[tid] = lw[tid];  // DD == 256 == blockDim
    if (tid < 4) sm.bits[tid] = 0u;
    __syncthreads();

    // ---- out[n] = x[n,:] . w ----
    for (int n = wid; n < NN; n += 8) {
        const float* xr = xB + n * DD;
        float s = 0.f;
        #pragma unroll
        for (int t = 0; t < DD / 32; ++t)
            s = fmaf(xr[lane + 32 * t], sm.w[lane + 32 * t], s);
        #pragma unroll
        for (int o = 16; o > 0; o >>= 1) s += __shfl_down_sync(0xffffffffu, s, o);
        if (lane == 0) sm.outv[n] = s;
    }
    // ---- degree / dis / mask (adj from global, coalesced) ----
    for (int i = wid; i < NN; i += 8) {
        const float* ar = adjB + i * NN;
        float s = 0.f;
        #pragma unroll
        for (int t = 0; t < NN / 32; ++t) s += ar[lane + 32 * t];
        #pragma unroll
        for (int o = 16; o > 0; o >>= 1) s += __shfl_down_sync(0xffffffffu, s, o);
        if (lane == 0) {
            float deg = s + 1.0f;
            float dv  = rsqrtf(fmaxf(deg, 1.0f));
            sm.dis[i]  = dv;
            sm.rfac[i] = (s > 0.f) ? dv : 0.f;
        }
    }
    __syncthreads();

    if (tid < NN) sm.tvec[tid] = sm.dis[tid] * sm.outv[tid];
    {
        int v0 = head[(size_t)b * TT + tid];
        int v1 = head[(size_t)b * TT + 256 + tid];
        atomicOr(&sm.bits[v0 >> 5], 1u << (v0 & 31));
        atomicOr(&sm.bits[v1 >> 5], 1u << (v1 & 31));
    }
    __syncthreads();

    // ---- o2 = norm_adj @ out + bias ; alpha = sigmoid(o2^2) ----
    {
        const float biasv = bias[0];
        for (int i = wid; i < NN; i += 8) {
            const float* ar = adjB + i * NN;
            float s = 0.f;
            #pragma unroll
            for (int t = 0; t < NN / 32; ++t)
                s = fmaf(ar[lane + 32 * t], sm.tvec[lane + 32 * t], s);
            #pragma unroll
            for (int o = 16; o > 0; o >>= 1) s += __shfl_down_sync(0xffffffffu, s, o);
            if (lane == 0) {
                float o2 = fmaf(sm.rfac[i], s + sm.tvec[i], biasv);
                float q  = o2 * o2;
                sm.alpha[i] = 1.0f / (1.0f + expf(-q));
            }
        }
    }
    if (tid == 0) {
        int nu = __popc(sm.bits[0]) + __popc(sm.bits[1]) +
                 __popc(sm.bits[2]) + __popc(sm.bits[3]);
        sm.nuniq = nu;
        int k   = (int)ceilf((float)nu * 0.1f) + 1;
        int idx = k - 1;
        if (idx < 0) idx = 0;
        if (idx > NN - 1) idx = NN - 1;
        sm.kidx = idx;
    }
    __syncthreads();

    // ---- cut = k-th largest alpha (rank with stable tie-break) ----
    if (tid < NN) {
        float ai = sm.alpha[tid];
        int cnt = 0;
        #pragma unroll 8
        for (int j = 0; j < NN; ++j) {
            float aj = sm.alpha[j];
            cnt += (aj > ai) || (aj == ai && j < tid);
        }
        if (cnt == sm.kidx) sm.cutv = (sm.nuniq > 1) ? ai : 0.f;
    }
    __syncthreads();
    if (tid < NN) {
        float ca = fmaxf(sm.alpha[tid] + 1e-7f - sm.cutv, 0.f);
        sm.colfac[tid] = sm.dis[tid] * ca;
    }
    __syncthreads();

    // ---- build S: S[i,j] = rfac[i]*(adj+I)_ij*colfac[j], row-L1-normalized ----
    for (int i = wid; i < NN; i += 8) {
        const float* ar = adjB + i * NN;
        float v[NN / 32];
        float s = 0.f;
        #pragma unroll
        for (int t = 0; t < NN / 32; ++t) {
            int j = lane + 32 * t;
            float a = ar[j] + ((j == i) ? 1.f : 0.f);
            v[t] = a * sm.colfac[j];
            s += v[t];
        }
        #pragma unroll
        for (int o = 16; o > 0; o >>= 1) s += __shfl_down_sync(0xffffffffu, s, o);
        s = __shfl_sync(0xffffffffu, s, 0);
        float rf  = sm.rfac[i];
        float tot = rf * s;                       // L1 row sum (all nonneg)
        float r2  = rf / fmaxf(tot, 1e-12f);
        #pragma unroll
        for (int t = 0; t < NN / 32; ++t)
            sm.S[i][lane + 32 * t] = r2 * v[t];
    }
    __syncthreads();

    const int ty = tid >> 4, tx = tid & 15;
    const int i0 = ty * 8;

    // ---- GEMM1: emb = S^T @ x  (4 chunks of 64 d-cols through X) ----
    // Software-pipelined: prefetch k+1 operands before k's FMA2s.
    // (Last-iteration prefetch reads row NN — inside the smem struct, unused.)
    {
        float* embB = emb + (size_t)b * NN * DD;
        const int dd = tx * 4;
        for (int dc = 0; dc < 4; ++dc) {
            const int d0 = dc * 64;
            for (int idx = tid; idx < NN * 16; idx += 256) {
                int k = idx >> 4, c = (idx & 15) << 2;
                *reinterpret_cast<float4*>(&sm.X[k][c]) =
                    *reinterpret_cast<const float4*>(&xB[k * DD + d0 + c]);
            }
            __syncthreads();
            u64t acc[4][4];
            #pragma unroll
            for (int p = 0; p < 4; ++p)
                #pragma unroll
                for (int c = 0; c < 4; ++c) acc[p][c] = 0ull;

            ulonglong2 cA0 = *reinterpret_cast<ulonglong2*>(&sm.S[0][i0]);
            ulonglong2 cA1 = *reinterpret_cast<ulonglong2*>(&sm.S[0][i0 + 4]);
            float4     cB  = *reinterpret_cast<float4*>(&sm.X[0][dd]);
            #pragma unroll 4
            for (int k = 0; k < NN; ++k) {
                ulonglong2 nA0 = *reinterpret_cast<ulonglong2*>(&sm.S[k + 1][i0]);
                ulonglong2 nA1 = *reinterpret_cast<ulonglong2*>(&sm.S[k + 1][i0 + 4]);
                float4     nB  = *reinterpret_cast<float4*>(&sm.X[k + 1][dd]);
                u64t Bp[4];
                PACK2(Bp[0], cB.x); PACK2(Bp[1], cB.y);
                PACK2(Bp[2], cB.z); PACK2(Bp[3], cB.w);
                u64t Ap[4] = {cA0.x, cA0.y, cA1.x, cA1.y};
                #pragma unroll
                for (int p = 0; p < 4; ++p)
                    #pragma unroll
                    for (int c = 0; c < 4; ++c)
                        FMA2(acc[p][c], Ap[p], Bp[c]);
                cA0 = nA0; cA1 = nA1; cB = nB;
            }
            #pragma unroll
            for (int p = 0; p < 4; ++p) {
                float4 v0 = {lo32(acc[p][0]), lo32(acc[p][1]), lo32(acc[p][2]), lo32(acc[p][3])};
                float4 v1 = {hi32(acc[p][0]), hi32(acc[p][1]), hi32(acc[p][2]), hi32(acc[p][3])};
                *reinterpret_cast<float4*>(&embB[(i0 + 2 * p)     * DD + d0 + dd]) = v0;
                *reinterpret_cast<float4*>(&embB[(i0 + 2 * p + 1) * DD + d0 + dd]) = v1;
            }
            __syncthreads();
        }
    }

    // ---- new_adj = S^T (adj S): per 64-col chunk, Y = adj@S_chunk into X,
    //      then nadj_chunk = S^T @ Y ----
    {
        float* nadjB = nadj + (size_t)b * NN * NN;
        const int jj = tx * 4;
        for (int jc = 0; jc < 2; ++jc) {
            const int j0 = jc * 64;

            // Y[i0..i0+7, jj..jj+3] = adj @ S[:, j0:j0+64]
            // adj LDGs batched at iter top (MLP 8-16), S pack prefetched.
            u64t accY[8][2];
            #pragma unroll
            for (int r = 0; r < 8; ++r) { accY[r][0] = 0ull; accY[r][1] = 0ull; }
            ulonglong2 cBk[4];
            #pragma unroll
            for (int kk = 0; kk < 4; ++kk)
                cBk[kk] = *reinterpret_cast<ulonglong2*>(&sm.S[kk][j0 + jj]);
            #pragma unroll 2
            for (int k4 = 0; k4 < NN; k4 += 4) {
                float4 av[8];
                #pragma unroll
                for (int r = 0; r < 8; ++r)
                    av[r] = *reinterpret_cast<const float4*>(&adjB[(i0 + r) * NN + k4]);
                ulonglong2 nBk[4];
                #pragma unroll
                for (int kk = 0; kk < 4; ++kk)
                    nBk[kk] = *reinterpret_cast<ulonglong2*>(&sm.S[k4 + 4 + kk][j0 + jj]);
                #pragma unroll
                for (int kk = 0; kk < 4; ++kk) {
                    #pragma unroll
                    for (int r = 0; r < 8; ++r) {
                        float as = (kk == 0) ? av[r].x : (kk == 1) ? av[r].y
                                 : (kk == 2) ? av[r].z : av[r].w;
                        u64t pa;
                        PACK2(pa, as);
                        FMA2(accY[r][0], pa, cBk[kk].x);
                        FMA2(accY[r][1], pa, cBk[kk].y);
                    }
                }
                #pragma unroll
                for (int kk = 0; kk < 4; ++kk) cBk[kk] = nBk[kk];
            }
            __syncthreads();   // previous readers of X are done
            #pragma unroll
            for (int r = 0; r < 8; ++r) {
                float4 v = {lo32(accY[r][0]), hi32(accY[r][0]),
                            lo32(accY[r][1]), hi32(accY[r][1])};
                *reinterpret_cast<float4*>(&sm.X[i0 + r][jj]) = v;
            }
            __syncthreads();

            // nadj[:, j0:j0+64] = S^T @ Y   (row-pair packed, pipelined)
            u64t acc[4][4];
            #pragma unroll
            for (int p = 0; p < 4; ++p)
                #pragma unroll
                for (int c = 0; c < 4; ++c) acc[p][c] = 0ull;
            ulonglong2 cA0 = *reinterpret_cast<ulonglong2*>(&sm.S[0][i0]);
            ulonglong2 cA1 = *reinterpret_cast<ulonglong2*>(&sm.S[0][i0 + 4]);
            float4     cB  = *reinterpret_cast<float4*>(&sm.X[0][jj]);
            #pragma unroll 4
            for (int k = 0; k < NN; ++k) {
                ulonglong2 nA0 = *reinterpret_cast<ulonglong2*>(&sm.S[k + 1][i0]);
                ulonglong2 nA1 = *reinterpret_cast<ulonglong2*>(&sm.S[k + 1][i0 + 4]);
                float4     nB  = *reinterpret_cast<float4*>(&sm.X[k + 1][jj]);
                u64t Bp[4];
                PACK2(Bp[0], cB.x); PACK2(Bp[1], cB.y);
                PACK2(Bp[2], cB.z); PACK2(Bp[3], cB.w);
                u64t Ap[4] = {cA0.x, cA0.y, cA1.x, cA1.y};
                #pragma unroll
                for (int p = 0; p < 4; ++p)
                    #pragma unroll
                    for (int c = 0; c < 4; ++c)
                        FMA2(acc[p][c], Ap[p], Bp[c]);
                cA0 = nA0; cA1 = nA1; cB = nB;
            }
            #pragma unroll
            for (int p = 0; p < 4; ++p) {
                float4 v0 = {lo32(acc[p][0]), lo32(acc[p][1]), lo32(acc[p][2]), lo32(acc[p][3])};
                float4 v1 = {hi32(acc[p][0]), hi32(acc[p][1]), hi32(acc[p][2]), hi32(acc[p][3])};
                *reinterpret_cast<float4*>(&nadjB[(i0 + 2 * p)     * NN + j0 + jj]) = v0;
                *reinterpret_cast<float4*>(&nadjB[(i0 + 2 * p + 1) * NN + j0 + jj]) = v1;
            }
            __syncthreads();
        }
    }
}

extern "C" void kernel_launch(void* const* d_in, const int* in_sizes, int n_in,
                              void* d_out, int out_size) {
    const float* x    = (const float*)d_in[0];   // concept_hidden [B,N,D]
    const float* adj  = (const float*)d_in[1];   // adj [B,N,N]
    const int*   head = (const int*)d_in[2];     // head [B,T]
    const float* lw   = (const float*)d_in[3];   // lin_w [1,D]
    const float* bias = (const float*)d_in[4];   // bias [1]

    float* out  = (float*)d_out;
    float* emb  = out;                                  // [B,N,D]
    float* nadj = out + (size_t)BB * NN * DD;           // [B,N,N]

    const int smemBytes = (int)sizeof(Smem);
    cudaFuncSetAttribute(graph_coarsen_kernel,
                         cudaFuncAttributeMaxDynamicSharedMemorySize, smemBytes);
    graph_coarsen_kernel<<<BB, 256, smemBytes>>>(x, adj, head, lw, bias, emb, nadj);
}